// round 5
// baseline (speedup 1.0000x reference)
#include <cuda_runtime.h>

// InverseHaar: input (B=16, C=256, H=128, W=128) fp32, C = 4 bands x G=64 groups.
// Output (B=16, G=64, 2H=256, 2W=256) fp32.
//
// R2 shape (best measured DRAM%): lane l of a warp owns input w pairs
// {2l,2l+1} and {64+2l,64+2l+1} of one (b,g,h) row -> 8 front-batched LDG.64
// (512B/warp/band, MLP=8), 4 STG.128 each warp-contiguous 512B covering 2KB
// of sequential output per warp. Block=512 to halve CTA count.

#define B_  16
#define G_  64
#define H_  128
#define W_  128
#define HW_ (H_ * W_)              // 16384
#define BAND_STRIDE_ (G_ * HW_)    // 1048576 floats between bands (same b)
#define OW_ (2 * W_)               // 256 output width
#define OH_ (2 * H_)               // 256 output height

__global__ void __launch_bounds__(512) inverse_haar_kernel(
    const float2* __restrict__ in,   // viewed as float2
    float4* __restrict__ out)        // viewed as float4
{
    int idx = blockIdx.x * blockDim.x + threadIdx.x;
    // total threads = B*G*H*32 = 4,194,304 (32 lanes cover one full input row)

    int l  = idx & 31;            // lane-role within a row
    int t  = idx >> 5;
    int h  = t & (H_ - 1);
    t >>= 7;
    int g  = t & (G_ - 1);
    int b  = t >> 6;

    // Input base in float2 units: band a, (b,g,h) row, element pair l (w=2l,2l+1)
    long base = ((long)(b * 4) * G_ + g) * (HW_ / 2) + (long)h * (W_ / 2) + l;
    const long S = BAND_STRIDE_ / 2;   // band stride in float2 units
    const int  HALF = 32;              // second half-row offset (w=64)

    // 8 independent streaming loads -> MLP=8
    float2 a0 = __ldcs(&in[base]);
    float2 a1 = __ldcs(&in[base + HALF]);
    float2 h0 = __ldcs(&in[base + S]);
    float2 h1 = __ldcs(&in[base + S + HALF]);
    float2 v0 = __ldcs(&in[base + 2 * S]);
    float2 v1 = __ldcs(&in[base + 2 * S + HALF]);
    float2 d0 = __ldcs(&in[base + 3 * S]);
    float2 d1 = __ldcs(&in[base + 3 * S + HALF]);

    const float Q = 0.25f;

    // group 0: w = 2l (x), 2l+1 (y)
    float tl0x = (a0.x + h0.x + v0.x + d0.x) * Q;
    float tr0x = (a0.x - h0.x + v0.x - d0.x) * Q;
    float bl0x = (a0.x + h0.x - v0.x - d0.x) * Q;
    float br0x = (a0.x - h0.x - v0.x + d0.x) * Q;

    float tl0y = (a0.y + h0.y + v0.y + d0.y) * Q;
    float tr0y = (a0.y - h0.y + v0.y - d0.y) * Q;
    float bl0y = (a0.y + h0.y - v0.y - d0.y) * Q;
    float br0y = (a0.y - h0.y - v0.y + d0.y) * Q;

    // group 1: w = 64+2l (x), 64+2l+1 (y)
    float tl1x = (a1.x + h1.x + v1.x + d1.x) * Q;
    float tr1x = (a1.x - h1.x + v1.x - d1.x) * Q;
    float bl1x = (a1.x + h1.x - v1.x - d1.x) * Q;
    float br1x = (a1.x - h1.x - v1.x + d1.x) * Q;

    float tl1y = (a1.y + h1.y + v1.y + d1.y) * Q;
    float tr1y = (a1.y - h1.y + v1.y - d1.y) * Q;
    float bl1y = (a1.y + h1.y - v1.y - d1.y) * Q;
    float br1y = (a1.y - h1.y - v1.y + d1.y) * Q;

    // Output row bases (float4 units). Row has OW_/4 = 64 float4.
    long orow0 = (((long)(b * G_ + g) * OH_) + 2 * h) * (OW_ / 4) + l;
    long orow1 = orow0 + (OW_ / 4);

    // Each store: lanes 0..31 hit consecutive 16B slots -> contiguous 512B.
    __stcs(&out[orow0],      make_float4(tl0x, tr0x, tl0y, tr0y));
    __stcs(&out[orow0 + 32], make_float4(tl1x, tr1x, tl1y, tr1y));
    __stcs(&out[orow1],      make_float4(bl0x, br0x, bl0y, br0y));
    __stcs(&out[orow1 + 32], make_float4(bl1x, br1x, bl1y, br1y));
}

extern "C" void kernel_launch(void* const* d_in, const int* in_sizes, int n_in,
                              void* d_out, int out_size)
{
    const float2* in = (const float2*)d_in[0];
    float4* out = (float4*)d_out;

    int total_threads = B_ * G_ * H_ * 32;   // 4,194,304
    int block = 512;
    int grid = total_threads / block;        // 8192
    inverse_haar_kernel<<<grid, block>>>(in, out);
}